// round 2
// baseline (speedup 1.0000x reference)
#include <cuda_runtime.h>

// Problem constants (static per reference)
#define NGR 4
#define GF 256
#define DIN 834
#define SS 1568
#define NB 16
#define TOT 160
#define IDIM 1024
#define NMAX 16

// ---------------- scratch (static device globals; no runtime allocs) -------
__device__ float g_emb[TOT * NGR * GF];            // [t][g][f]
__device__ float g_ctx[NB * NGR * GF * SS];        // [b][g][f][s]  ~103MB
__device__ float g_adj[NB * NGR * NMAX * SS];      // [b][g][n][s]
__device__ float g_flat[TOT * NGR * GF];           // [t][g][f]
__device__ int   g_off[NB];
__device__ int   g_cnt[NB];

// ---------------- K0: ragged bookkeeping, dtype-autodetecting --------------
// counts may arrive as int32 (harness-normalized) or int64 (original numpy).
// int32 interpretation is accepted iff all values in [0, NMAX] and sum == TOT.
// (int64 data viewed as int32 interleaves zero words -> sum mismatch -> reject.)
__global__ void init_offsets_k(const void* __restrict__ counts) {
    if (threadIdx.x == 0 && blockIdx.x == 0) {
        const int* c32 = (const int*)counts;
        const long long* c64 = (const long long*)counts;
        long long s = 0;
        bool ok32 = true;
        for (int b = 0; b < NB; b++) {
            int v = c32[b];
            if (v < 0 || v > NMAX) ok32 = false;
            s += v;
        }
        if (s != TOT) ok32 = false;
        int acc = 0;
        for (int b = 0; b < NB; b++) {
            int c = ok32 ? c32[b] : (int)c64[b];
            if (c < 0) c = 0;
            if (c > NMAX) c = NMAX;
            g_off[b] = acc;
            g_cnt[b] = c;
            acc += c;
        }
    }
}

// ---------------- generic GEMM: C[M][N] = A[M][K] * B[N][K]^T (+bias,+relu) -
// 32x64 tile, BK=32, 256 threads, 8 outputs/thread.
__global__ void __launch_bounds__(256) gemm_nt_k(
    const float* __restrict__ A, int lda, long long aZ,
    const float* __restrict__ Bm, int ldb, long long bZ,
    const float* __restrict__ bias,
    float* __restrict__ C, int ldc, long long cZ,
    int K, int doRelu)
{
    int z = blockIdx.z;
    A  += (long long)z * aZ;
    Bm += (long long)z * bZ;
    C  += (long long)z * cZ;

    __shared__ __align__(16) float As[32][33];   // [k][m]
    __shared__ __align__(16) float Bs[32][65];   // [k][n]

    int tid = threadIdx.x;
    int m0 = blockIdx.x * 32;
    int n0 = blockIdx.y * 64;
    int tx = tid % 64;       // n
    int ty = tid / 64;       // m group (0..3)

    float acc[8];
#pragma unroll
    for (int i = 0; i < 8; i++) acc[i] = 0.f;

    for (int k0 = 0; k0 < K; k0 += 32) {
#pragma unroll
        for (int t = 0; t < 4; t++) {          // A tile: 32m x 32k
            int lin = tid + 256 * t;
            int k = lin & 31, m = lin >> 5;
            As[k][m] = A[(m0 + m) * (long long)lda + k0 + k];
        }
#pragma unroll
        for (int t = 0; t < 8; t++) {          // B tile: 64n x 32k
            int lin = tid + 256 * t;
            int k = lin & 31, n = lin >> 5;
            Bs[k][n] = Bm[(n0 + n) * (long long)ldb + k0 + k];
        }
        __syncthreads();
#pragma unroll
        for (int k = 0; k < 32; k++) {
            float bv = Bs[k][tx];
#pragma unroll
            for (int i = 0; i < 8; i++)
                acc[i] += As[k][ty + 4 * i] * bv;
        }
        __syncthreads();
    }

    float bb = bias ? bias[n0 + tx] : 0.f;
#pragma unroll
    for (int i = 0; i < 8; i++) {
        int m = m0 + ty + 4 * i;
        float v = acc[i] + bb;
        if (doRelu) v = fmaxf(v, 0.f);
        C[m * (long long)ldc + n0 + tx] = v;
    }
}

// ---------------- K2: ctx[b,g,f,s] = sum_c W_c[g,f,c]*fm[b,c,s] + b_c[g,f] --
// 128x128x8 SGEMM, 8x8 per thread, grid (13, 2, 64)
__global__ void __launch_bounds__(256) ctx_gemm_k(
    const float* __restrict__ Wc, const float* __restrict__ fm,
    const float* __restrict__ bc)
{
    int z = blockIdx.z;
    int b = z >> 2, g = z & 3;
    const float* A = Wc + (long long)g * GF * DIN;     // [256][834]
    const float* B = fm + (long long)b * DIN * SS;     // [834][1568]
    float* C = g_ctx + (long long)z * GF * SS;
    const float* bias = bc + g * GF;

    __shared__ __align__(16) float As[8][128];   // [k][m]
    __shared__ __align__(16) float Bs[8][128];   // [k][n]

    int tid = threadIdx.x;
    int m0 = blockIdx.y * 128;
    int n0 = blockIdx.x * 128;
    int tx = tid % 16, ty = tid / 16;

    float acc[8][8];
#pragma unroll
    for (int i = 0; i < 8; i++)
#pragma unroll
        for (int j = 0; j < 8; j++) acc[i][j] = 0.f;

    for (int k0 = 0; k0 < DIN; k0 += 8) {
#pragma unroll
        for (int t = 0; t < 4; t++) {          // A: 128m x 8k
            int lin = tid + 256 * t;
            int k = lin & 7, m = lin >> 3;
            float v = 0.f;
            if (k0 + k < DIN) v = A[(m0 + m) * DIN + k0 + k];
            As[k][m] = v;
        }
#pragma unroll
        for (int t = 0; t < 4; t++) {          // B: 8k x 128n
            int lin = tid + 256 * t;
            int n = lin & 127, k = lin >> 7;
            float v = 0.f;
            if (k0 + k < DIN && n0 + n < SS) v = B[(k0 + k) * SS + n0 + n];
            Bs[k][n] = v;
        }
        __syncthreads();
#pragma unroll
        for (int k = 0; k < 8; k++) {
            float a[8], bv[8];
            *(float4*)&a[0]  = *(const float4*)&As[k][ty * 8];
            *(float4*)&a[4]  = *(const float4*)&As[k][ty * 8 + 4];
            *(float4*)&bv[0] = *(const float4*)&Bs[k][tx * 8];
            *(float4*)&bv[4] = *(const float4*)&Bs[k][tx * 8 + 4];
#pragma unroll
            for (int i = 0; i < 8; i++)
#pragma unroll
                for (int j = 0; j < 8; j++)
                    acc[i][j] += a[i] * bv[j];
        }
        __syncthreads();
    }

#pragma unroll
    for (int i = 0; i < 8; i++) {
        int m = m0 + ty * 8 + i;
        float bb = bias[m];
#pragma unroll
        for (int j = 0; j < 8; j++) {
            int n = n0 + tx * 8 + j;
            if (n < SS) C[m * SS + n] = acc[i][j] + bb;
        }
    }
}

// ---------------- K3: adj[b,g,n,s] = sum_f emb_pad[b,n,g,f]*ctx[b,g,f,s] ----
__global__ void __launch_bounds__(256) adj_logits_k() {
    int g = blockIdx.y, b = blockIdx.z;
    __shared__ __align__(16) float a_s[GF * NMAX];   // [f][n]
    int tid = threadIdx.x;
    int cnt = g_cnt[b], off = g_off[b];

    for (int idx = tid; idx < GF * NMAX; idx += 256) {
        int n = idx >> 8, f = idx & 255;
        float v = 0.f;
        if (n < cnt) v = g_emb[(off + n) * (NGR * GF) + g * GF + f];
        a_s[f * NMAX + n] = v;
    }
    __syncthreads();

    int s = blockIdx.x * 256 + tid;
    if (s >= SS) return;

    const float* ctxp = g_ctx + ((long long)(b * NGR + g)) * GF * SS + s;
    float acc[NMAX];
#pragma unroll
    for (int n = 0; n < NMAX; n++) acc[n] = 0.f;

    const float4* ap = (const float4*)a_s;
#pragma unroll 4
    for (int f = 0; f < GF; f++) {
        float v = ctxp[f * SS];
        float4 a0 = ap[f * 4 + 0];
        float4 a1 = ap[f * 4 + 1];
        float4 a2 = ap[f * 4 + 2];
        float4 a3 = ap[f * 4 + 3];
        acc[0]  += v * a0.x;  acc[1]  += v * a0.y;  acc[2]  += v * a0.z;  acc[3]  += v * a0.w;
        acc[4]  += v * a1.x;  acc[5]  += v * a1.y;  acc[6]  += v * a1.z;  acc[7]  += v * a1.w;
        acc[8]  += v * a2.x;  acc[9]  += v * a2.y;  acc[10] += v * a2.z;  acc[11] += v * a2.w;
        acc[12] += v * a3.x;  acc[13] += v * a3.y;  acc[14] += v * a3.z;  acc[15] += v * a3.w;
    }

    float* adjp = g_adj + ((long long)(b * NGR + g)) * NMAX * SS + s;
#pragma unroll
    for (int n = 0; n < NMAX; n++) adjp[n * SS] = acc[n];
}

// ---------------- K4: softmax over s per valid (b,g,n) row ------------------
__global__ void __launch_bounds__(256) softmax_k() {
    int n = blockIdx.x, g = blockIdx.y, b = blockIdx.z;
    if (n >= g_cnt[b]) return;  // block-uniform
    float* row = g_adj + ((long long)((b * NGR + g) * NMAX + n)) * SS;
    int tid = threadIdx.x;
    __shared__ float red[8];

    float mx = -1e30f;
    for (int s = tid; s < SS; s += 256) mx = fmaxf(mx, row[s]);
#pragma unroll
    for (int o = 16; o > 0; o >>= 1) mx = fmaxf(mx, __shfl_xor_sync(0xffffffffu, mx, o));
    if ((tid & 31) == 0) red[tid >> 5] = mx;
    __syncthreads();
    if (tid < 32) {
        float v = (tid < 8) ? red[tid] : -1e30f;
#pragma unroll
        for (int o = 4; o > 0; o >>= 1) v = fmaxf(v, __shfl_xor_sync(0xffffffffu, v, o));
        if (tid == 0) red[0] = v;
    }
    __syncthreads();
    mx = red[0];
    __syncthreads();

    float sum = 0.f;
    for (int s = tid; s < SS; s += 256) {
        float e = __expf(row[s] - mx);
        row[s] = e;
        sum += e;
    }
#pragma unroll
    for (int o = 16; o > 0; o >>= 1) sum += __shfl_xor_sync(0xffffffffu, sum, o);
    if ((tid & 31) == 0) red[tid >> 5] = sum;
    __syncthreads();
    if (tid < 32) {
        float v = (tid < 8) ? red[tid] : 0.f;
#pragma unroll
        for (int o = 4; o > 0; o >>= 1) v += __shfl_xor_sync(0xffffffffu, v, o);
        if (tid == 0) red[0] = v;
    }
    __syncthreads();
    float inv = 1.f / red[0];
    for (int s = tid; s < SS; s += 256) row[s] *= inv;
}

// ---------------- K5: flat[t,g,f] = sum_s adj[b,g,n,s]*ctx[b,g,f,s] + emb ---
__global__ void __launch_bounds__(256) aggregate_k() {
    int z = blockIdx.y;
    int b = z >> 2, g = z & 3;
    int f0 = blockIdx.x * 64;

    __shared__ __align__(16) float adjS[NMAX][33];
    __shared__ __align__(16) float ctxS[32][65];

    const float* adjp = g_adj + (long long)z * NMAX * SS;
    const float* ctxp = g_ctx + (long long)z * GF * SS;

    int tid = threadIdx.x;
    int fid = tid % 64, grp = tid / 64;
    float acc[4] = {0.f, 0.f, 0.f, 0.f};

    for (int s0 = 0; s0 < SS; s0 += 32) {
#pragma unroll
        for (int t = 0; t < 2; t++) {          // adj tile: 16n x 32s
            int lin = tid + 256 * t;
            int k = lin & 31, n = lin >> 5;
            adjS[n][k] = adjp[n * SS + s0 + k];
        }
#pragma unroll
        for (int t = 0; t < 8; t++) {          // ctx tile: 64f x 32s -> [s][f]
            int lin = tid + 256 * t;
            int k = lin & 31, i = lin >> 5;
            ctxS[k][i] = ctxp[(f0 + i) * SS + s0 + k];
        }
        __syncthreads();
#pragma unroll
        for (int k = 0; k < 32; k++) {
            float bv = ctxS[k][fid];
#pragma unroll
            for (int j = 0; j < 4; j++)
                acc[j] += adjS[grp * 4 + j][k] * bv;
        }
        __syncthreads();
    }

    int cnt = g_cnt[b], off = g_off[b];
#pragma unroll
    for (int j = 0; j < 4; j++) {
        int n = grp * 4 + j;
        if (n < cnt) {
            long long idx = (long long)(off + n) * (NGR * GF) + g * GF + f0 + fid;
            g_flat[idx] = acc[j] + g_emb[idx];
        }
    }
}

// ---------------- launch ----------------------------------------------------
extern "C" void kernel_launch(void* const* d_in, const int* in_sizes, int n_in,
                              void* d_out, int out_size) {
    // Resolve inputs by element count (robust to metadata ordering).
    // Sizes: actor=163840, fmap=20923392, W_a=1048576, W_c=854016,
    //        W_h=262144, b_a/b_c=1024 (both zeros; order-insensitive), counts=16.
    const float* actor = (const float*)d_in[0];
    const float* fmap  = (const float*)d_in[1];
    const float* W_a   = (const float*)d_in[2];
    const float* b_a   = (const float*)d_in[3];
    const float* W_c   = (const float*)d_in[4];
    const float* b_c   = (const float*)d_in[5];
    const float* W_h   = (const float*)d_in[6];
    const void*  counts = d_in[7];
    int nbias = 0;
    for (int i = 0; i < n_in; i++) {
        switch (in_sizes[i]) {
            case TOT * IDIM:      actor = (const float*)d_in[i]; break;
            case NB * DIN * SS:   fmap  = (const float*)d_in[i]; break;
            case NGR * GF * IDIM: W_a   = (const float*)d_in[i]; break;
            case NGR * GF * DIN:  W_c   = (const float*)d_in[i]; break;
            case NGR * GF * GF:   W_h   = (const float*)d_in[i]; break;
            case NGR * GF:
                if (nbias++ == 0) b_a = (const float*)d_in[i];
                else              b_c = (const float*)d_in[i];
                break;
            case NB:              counts = d_in[i]; break;
            default: break; // return_features (size 1) ignored
        }
    }
    float* out = (float*)d_out;                   // [160, 1024]

    float *emb_p, *flat_p;
    cudaGetSymbolAddress((void**)&emb_p, g_emb);
    cudaGetSymbolAddress((void**)&flat_p, g_flat);

    init_offsets_k<<<1, 32>>>(counts);

    // K1: emb[t][gf] = act . W_a^T + b_a   (M=160, N=1024, K=1024)
    gemm_nt_k<<<dim3(5, 16, 1), 256>>>(actor, IDIM, 0,
                                       W_a, IDIM, 0,
                                       b_a,
                                       emb_p, NGR * GF, 0,
                                       IDIM, 0);

    // K2: ctx (dominant GEMM)
    ctx_gemm_k<<<dim3(13, 2, 64), 256>>>(W_c, fmap, b_c);

    // K3: adjacency logits
    adj_logits_k<<<dim3(7, NGR, NB), 256>>>();

    // K4: softmax over context locations
    softmax_k<<<dim3(NMAX, NGR, NB), 256>>>();

    // K5: aggregate + residual, scatter to ragged flat
    aggregate_k<<<dim3(4, 64), 256>>>();

    // K6: head linear + relu  (per-g GEMM, M=160, N=256, K=256)
    gemm_nt_k<<<dim3(5, 4, 4), 256>>>(flat_p, NGR * GF, GF,
                                      W_h, GF, (long long)GF * GF,
                                      nullptr,
                                      out, NGR * GF, GF,
                                      GF, 1);
}